// round 1
// baseline (speedup 1.0000x reference)
#include <cuda_runtime.h>
#include <cuda_bf16.h>
#include <stdint.h>

// Problem constants (fixed by the dataset)
#define NN      100000
#define EE_MAX  1600000
#define IC      128
#define HID     128
#define OC      10

// ---------------- static scratch (no allocations allowed) ----------------
__device__ float g_deg [NN];
__device__ float g_dinv[NN];
__device__ float g_xw  [(size_t)NN * HID];   // h0 @ W1
__device__ float g_agg [(size_t)NN * HID];   // aggregated, then relu'd in place (= h1)
__device__ float g_t2  [(size_t)NN * OC];    // h1 @ W2
__device__ int   g_is64;

// ---------------- dtype detection for edge_index (int64 vs int32) --------
__global__ void k_detect(const void* eidx) {
    if (threadIdx.x == 0 && blockIdx.x == 0) {
        const unsigned long long* p = (const unsigned long long*)eidx;
        int is64 = 1;
        #pragma unroll 4
        for (int i = 0; i < 256; i++) {
            if (p[i] >> 32) { is64 = 0; break; }   // node ids < 100000 -> high word 0 iff i64
        }
        g_is64 = is64;
    }
}

__device__ __forceinline__ int edge_at(const void* eidx, long long off) {
    return g_is64 ? (int)((const long long*)eidx)[off]
                  : ((const int*)eidx)[off];
}

// ---------------- init: deg=1 (self loop), zero agg, zero out -------------
__global__ void k_init(float* __restrict__ out) {
    int i = blockIdx.x * blockDim.x + threadIdx.x;
    if (i < (int)(NN * HID)) g_agg[i] = 0.f;
    if (i < NN * OC)         out[i]   = 0.f;
    if (i < NN)              g_deg[i] = 1.0f;
}

// ---------------- degree (in-degree over dst) -----------------------------
__global__ void k_deg(const void* eidx, int E) {
    int e = blockIdx.x * blockDim.x + threadIdx.x;
    if (e >= E) return;
    int d = edge_at(eidx, (long long)E + e);
    atomicAdd(&g_deg[d], 1.0f);
}

__global__ void k_dinv() {
    int i = blockIdx.x * blockDim.x + threadIdx.x;
    if (i < NN) g_dinv[i] = rsqrtf(g_deg[i]);   // deg >= 1 always (self loop)
}

// ---------------- GEMM1: g_xw = [x - a, a] @ W1  (M=100k, N=128, K=256) ---
#define BM 64
#define BK 16
#define BN 128
__global__ __launch_bounds__(256) void k_gemm1(const float* __restrict__ x,
                                               const float* __restrict__ anch,
                                               const float* __restrict__ W1) {
    __shared__ float As[BK][BM + 4];
    __shared__ float Bs[BK][BN];

    const int tid = threadIdx.x;            // 0..255
    const int block_row = blockIdx.x * BM;
    const int tx = tid & 15;                // col group: cols tx*8 .. tx*8+7
    const int ty = tid >> 4;                // row group: rows ty*4 .. ty*4+3

    float acc[4][8];
    #pragma unroll
    for (int i = 0; i < 4; i++)
        #pragma unroll
        for (int j = 0; j < 8; j++) acc[i][j] = 0.f;

    for (int kt = 0; kt < 2 * IC; kt += BK) {
        // --- A tile: 64 rows x 16 k; one float4 per thread ---
        {
            int r  = tid >> 2;
            int cq = tid & 3;
            int n  = block_row + r;
            int k  = kt + cq * 4;
            float4 v = make_float4(0.f, 0.f, 0.f, 0.f);
            if (n < NN) {
                if (k < IC) {
                    float4 a = __ldg((const float4*)(x    + (size_t)n * IC + k));
                    float4 b = __ldg((const float4*)(anch + (size_t)n * IC + k));
                    v = make_float4(a.x - b.x, a.y - b.y, a.z - b.z, a.w - b.w);
                } else {
                    v = __ldg((const float4*)(anch + (size_t)n * IC + (k - IC)));
                }
            }
            As[cq * 4 + 0][r] = v.x;
            As[cq * 4 + 1][r] = v.y;
            As[cq * 4 + 2][r] = v.z;
            As[cq * 4 + 3][r] = v.w;
        }
        // --- B tile: 16 x 128; two float4 per thread ---
        #pragma unroll
        for (int i = 0; i < 2; i++) {
            int e  = tid + i * 256;         // 0..511 (float4 index)
            int rr = e >> 5;                // row 0..15
            int cc = (e & 31) << 2;         // col 0..124 step 4
            float4 v = __ldg((const float4*)(W1 + (size_t)(kt + rr) * BN + cc));
            *((float4*)&Bs[rr][cc]) = v;
        }
        __syncthreads();

        #pragma unroll
        for (int k = 0; k < BK; k++) {
            float a[4], b[8];
            #pragma unroll
            for (int i = 0; i < 4; i++) a[i] = As[k][ty * 4 + i];
            #pragma unroll
            for (int j = 0; j < 8; j++) b[j] = Bs[k][tx * 8 + j];
            #pragma unroll
            for (int i = 0; i < 4; i++)
                #pragma unroll
                for (int j = 0; j < 8; j++)
                    acc[i][j] = fmaf(a[i], b[j], acc[i][j]);
        }
        __syncthreads();
    }

    #pragma unroll
    for (int i = 0; i < 4; i++) {
        int n = block_row + ty * 4 + i;
        if (n < NN) {
            float* row = g_xw + (size_t)n * HID + tx * 8;
            *((float4*)(row + 0)) = make_float4(acc[i][0], acc[i][1], acc[i][2], acc[i][3]);
            *((float4*)(row + 4)) = make_float4(acc[i][4], acc[i][5], acc[i][6], acc[i][7]);
        }
    }
}

// ---------------- scatter layer 1: warp per edge, vector RED -------------
__global__ __launch_bounds__(256) void k_scatter1(const void* __restrict__ eidx, int E) {
    int gwarp = (blockIdx.x * blockDim.x + threadIdx.x) >> 5;
    int lane  = threadIdx.x & 31;
    if (gwarp >= E) return;

    int s = edge_at(eidx, gwarp);
    int d = edge_at(eidx, (long long)E + gwarp);
    float norm = g_dinv[s] * g_dinv[d];

    float4 v = __ldg(((const float4*)(g_xw + (size_t)s * HID)) + lane);
    v.x *= norm; v.y *= norm; v.z *= norm; v.w *= norm;

    float* dst = g_agg + (size_t)d * HID + lane * 4;
    asm volatile("red.global.add.v4.f32 [%0], {%1, %2, %3, %4};"
                 :: "l"(dst), "f"(v.x), "f"(v.y), "f"(v.z), "f"(v.w)
                 : "memory");
}

// ---------------- epilogue 1: self loop + bias + relu (in place) ---------
__global__ void k_epi1(const float* __restrict__ b1) {
    int idx = blockIdx.x * blockDim.x + threadIdx.x;
    if (idx >= (int)(NN * HID)) return;
    int n = idx >> 7;             // /128
    int j = idx & 127;
    float di = g_dinv[n];
    float v = g_agg[idx] + g_xw[idx] * di * di + __ldg(&b1[j]);
    g_agg[idx] = fmaxf(v, 0.f);   // g_agg is now h1
}

// ---------------- GEMM2: g_t2 = h1 @ W2  (warp per node) -----------------
__global__ __launch_bounds__(256) void k_gemm2(const float* __restrict__ W2) {
    int gwarp = (blockIdx.x * blockDim.x + threadIdx.x) >> 5;
    int lane  = threadIdx.x & 31;
    if (gwarp >= NN) return;

    float4 h = __ldg(((const float4*)(g_agg + (size_t)gwarp * HID)) + lane);
    int k0 = lane * 4;
    #pragma unroll
    for (int j = 0; j < OC; j++) {
        float p = h.x * __ldg(&W2[(k0 + 0) * OC + j])
                + h.y * __ldg(&W2[(k0 + 1) * OC + j])
                + h.z * __ldg(&W2[(k0 + 2) * OC + j])
                + h.w * __ldg(&W2[(k0 + 3) * OC + j]);
        p += __shfl_down_sync(0xFFFFFFFFu, p, 16);
        p += __shfl_down_sync(0xFFFFFFFFu, p, 8);
        p += __shfl_down_sync(0xFFFFFFFFu, p, 4);
        p += __shfl_down_sync(0xFFFFFFFFu, p, 2);
        p += __shfl_down_sync(0xFFFFFFFFu, p, 1);
        if (lane == 0) g_t2[(size_t)gwarp * OC + j] = p;
    }
}

// ---------------- scatter layer 2: thread per edge, 5x float2 RED --------
__global__ void k_scatter2(const void* __restrict__ eidx, int E, float* __restrict__ out) {
    int e = blockIdx.x * blockDim.x + threadIdx.x;
    if (e >= E) return;
    int s = edge_at(eidx, e);
    int d = edge_at(eidx, (long long)E + e);
    float norm = g_dinv[s] * g_dinv[d];

    const float2* t = (const float2*)(g_t2 + (size_t)s * OC);  // 40B aligned to 8
    float*        o = out + (size_t)d * OC;
    #pragma unroll
    for (int i = 0; i < 5; i++) {
        float2 v = __ldg(t + i);
        v.x *= norm; v.y *= norm;
        asm volatile("red.global.add.v2.f32 [%0], {%1, %2};"
                     :: "l"(o + 2 * i), "f"(v.x), "f"(v.y)
                     : "memory");
    }
}

// ---------------- epilogue 2: self loop + bias ---------------------------
__global__ void k_epi2(const float* __restrict__ b2, float* __restrict__ out) {
    int idx = blockIdx.x * blockDim.x + threadIdx.x;
    if (idx >= NN * OC) return;
    int n = idx / OC;
    int j = idx - n * OC;
    float di = g_dinv[n];
    out[idx] = out[idx] + g_t2[idx] * di * di + __ldg(&b2[j]);
}

// ---------------- launch -------------------------------------------------
extern "C" void kernel_launch(void* const* d_in, const int* in_sizes, int n_in,
                              void* d_out, int out_size) {
    const float* x    = (const float*)d_in[0];
    const void*  eidx = d_in[1];
    // d_in[2] = labels (unused)
    const float* anch = (const float*)d_in[3];
    const float* W1   = (const float*)d_in[4];
    const float* b1   = (const float*)d_in[5];
    const float* W2   = (const float*)d_in[6];
    const float* b2   = (const float*)d_in[7];
    float*       out  = (float*)d_out;

    const int E = in_sizes[1] / 2;   // element count of edge_index / 2 (either dtype)

    k_detect<<<1, 32>>>(eidx);

    {   // init covers max(NN*HID, NN*OC, NN)
        int n = NN * HID;
        k_init<<<(n + 255) / 256, 256>>>(out);
    }

    k_deg<<<(E + 255) / 256, 256>>>(eidx, E);
    k_dinv<<<(NN + 255) / 256, 256>>>();

    k_gemm1<<<(NN + BM - 1) / BM, 256>>>(x, anch, W1);

    {   // one warp per edge
        long long threads = (long long)E * 32;
        k_scatter1<<<(unsigned)((threads + 255) / 256), 256>>>(eidx, E);
    }

    k_epi1<<<(NN * HID + 255) / 256, 256>>>(b1);

    {   // one warp per node
        long long threads = (long long)NN * 32;
        k_gemm2<<<(unsigned)((threads + 255) / 256), 256>>>(W2);
    }

    k_scatter2<<<(E + 255) / 256, 256>>>(eidx, E, out);
    k_epi2<<<(NN * OC + 255) / 256, 256>>>(b2, out);
}

// round 2
// speedup vs baseline: 1.5353x; 1.5353x over previous
#include <cuda_runtime.h>
#include <cuda_bf16.h>
#include <stdint.h>

// Problem constants (fixed by the dataset)
#define NN      100000
#define EE_MAX  1600000
#define IC      128
#define HID     128
#define OC      10
#define NB_SCAN 391          // ceil(NN/256)

// ---------------- static scratch (no allocations allowed) ----------------
__device__ float g_dinv[NN];
__device__ float g_xw  [(size_t)NN * HID];   // h0 @ W1
__device__ float g_t2  [(size_t)NN * OC];    // h1 @ W2 (pre-aggregation)
__device__ int   g_cnt [NN];                 // in-degree (excl. self loop)
__device__ int   g_excl[NN];                 // within-block exclusive scan
__device__ int   g_off [NN];                 // CSR row start
__device__ int   g_cur [NN];                 // bucket cursor
__device__ int   g_btot[NB_SCAN];
__device__ int   g_boff[NB_SCAN];
__device__ int2  g_ebuf[EE_MAX];             // {src, norm-as-bits} bucketed by dst
__device__ int   g_is64;

// ---------------- dtype detection for edge_index (int64 vs int32) --------
__global__ void k_detect(const void* eidx) {
    if (threadIdx.x == 0 && blockIdx.x == 0) {
        const unsigned long long* p = (const unsigned long long*)eidx;
        int is64 = 1;
        for (int i = 0; i < 256; i++) {
            if (p[i] >> 32) { is64 = 0; break; }  // ids < 100000 -> high word 0 iff i64
        }
        g_is64 = is64;
    }
}

__device__ __forceinline__ int edge_at(const void* eidx, long long off) {
    return g_is64 ? (int)((const long long*)eidx)[off]
                  : ((const int*)eidx)[off];
}

// ---------------- CSR build ----------------------------------------------
__global__ void k_zero() {
    int i = blockIdx.x * blockDim.x + threadIdx.x;
    if (i < NN) g_cnt[i] = 0;
}

__global__ void k_count(const void* __restrict__ eidx, int E) {
    int e = blockIdx.x * blockDim.x + threadIdx.x;
    if (e >= E) return;
    int d = edge_at(eidx, (long long)E + e);
    atomicAdd(&g_cnt[d], 1);
}

// per-block inclusive scan of counts; emit within-block exclusive + block total
__global__ __launch_bounds__(256) void k_scan1() {
    __shared__ int sh[256];
    int tid = threadIdx.x;
    int i = blockIdx.x * 256 + tid;
    int c = (i < NN) ? g_cnt[i] : 0;
    sh[tid] = c;
    __syncthreads();
    #pragma unroll
    for (int o = 1; o < 256; o <<= 1) {
        int v = (tid >= o) ? sh[tid - o] : 0;
        __syncthreads();
        sh[tid] += v;
        __syncthreads();
    }
    if (i < NN) g_excl[i] = sh[tid] - c;
    if (tid == 255) g_btot[blockIdx.x] = sh[255];
}

// scan of block totals (single block)
__global__ __launch_bounds__(512) void k_scan2() {
    __shared__ int sh[512];
    int tid = threadIdx.x;
    int t = (tid < NB_SCAN) ? g_btot[tid] : 0;
    sh[tid] = t;
    __syncthreads();
    #pragma unroll
    for (int o = 1; o < 512; o <<= 1) {
        int v = (tid >= o) ? sh[tid - o] : 0;
        __syncthreads();
        sh[tid] += v;
        __syncthreads();
    }
    if (tid < NB_SCAN) g_boff[tid] = sh[tid] - t;
}

// finalize offsets, cursors, dinv
__global__ void k_scan3() {
    int i = blockIdx.x * blockDim.x + threadIdx.x;
    if (i >= NN) return;
    int off = g_excl[i] + g_boff[i >> 8];
    g_off[i] = off;
    g_cur[i] = off;
    g_dinv[i] = rsqrtf((float)g_cnt[i] + 1.0f);  // +1 self loop
}

__global__ void k_bucket(const void* __restrict__ eidx, int E) {
    int e = blockIdx.x * blockDim.x + threadIdx.x;
    if (e >= E) return;
    int s = edge_at(eidx, e);
    int d = edge_at(eidx, (long long)E + e);
    int pos = atomicAdd(&g_cur[d], 1);
    float norm = g_dinv[s] * g_dinv[d];
    g_ebuf[pos] = make_int2(s, __float_as_int(norm));
}

// ---------------- GEMM1: g_xw = [x - a, a] @ W1  (M=100k, N=128, K=256) ---
#define G1_BM 128
#define G1_BN 128
#define G1_BK 8
__global__ __launch_bounds__(256) void k_gemm1(const float* __restrict__ x,
                                               const float* __restrict__ anch,
                                               const float* __restrict__ W1) {
    __shared__ float As[G1_BK][G1_BM];
    __shared__ float Bs[G1_BK][G1_BN];

    const int tid = threadIdx.x;
    const int row0 = blockIdx.x * G1_BM;
    const int tx = tid & 15;       // col tile: tx*8 .. tx*8+7
    const int ty = tid >> 4;       // row tile: ty*8 .. ty*8+7

    // A loader: 128 rows x 8 k, one float4/thread
    const int ar = tid >> 1;
    const int ak = (tid & 1) * 4;
    // B loader: 8 rows x 128 cols, one float4/thread
    const int br = tid >> 5;
    const int bc = (tid & 31) * 4;

    float acc[8][8];
    #pragma unroll
    for (int i = 0; i < 8; i++)
        #pragma unroll
        for (int j = 0; j < 8; j++) acc[i][j] = 0.f;

    for (int kt = 0; kt < 2 * IC; kt += G1_BK) {
        // --- A tile ---
        {
            int n = row0 + ar;
            int k = kt + ak;
            float4 v = make_float4(0.f, 0.f, 0.f, 0.f);
            if (n < NN) {
                if (k < IC) {
                    float4 a = __ldg((const float4*)(x    + (size_t)n * IC + k));
                    float4 b = __ldg((const float4*)(anch + (size_t)n * IC + k));
                    v = make_float4(a.x - b.x, a.y - b.y, a.z - b.z, a.w - b.w);
                } else {
                    v = __ldg((const float4*)(anch + (size_t)n * IC + (k - IC)));
                }
            }
            As[ak + 0][ar] = v.x;
            As[ak + 1][ar] = v.y;
            As[ak + 2][ar] = v.z;
            As[ak + 3][ar] = v.w;
        }
        // --- B tile ---
        {
            float4 w = __ldg((const float4*)(W1 + (size_t)(kt + br) * G1_BN + bc));
            *((float4*)&Bs[br][bc]) = w;
        }
        __syncthreads();

        #pragma unroll
        for (int k = 0; k < G1_BK; k++) {
            float a[8], b[8];
            *((float4*)(a + 0)) = *((const float4*)&As[k][ty * 8 + 0]);
            *((float4*)(a + 4)) = *((const float4*)&As[k][ty * 8 + 4]);
            *((float4*)(b + 0)) = *((const float4*)&Bs[k][tx * 8 + 0]);
            *((float4*)(b + 4)) = *((const float4*)&Bs[k][tx * 8 + 4]);
            #pragma unroll
            for (int i = 0; i < 8; i++)
                #pragma unroll
                for (int j = 0; j < 8; j++)
                    acc[i][j] = fmaf(a[i], b[j], acc[i][j]);
        }
        __syncthreads();
    }

    #pragma unroll
    for (int i = 0; i < 8; i++) {
        int n = row0 + ty * 8 + i;
        if (n < NN) {
            float* row = g_xw + (size_t)n * HID + tx * 8;
            *((float4*)(row + 0)) = make_float4(acc[i][0], acc[i][1], acc[i][2], acc[i][3]);
            *((float4*)(row + 4)) = make_float4(acc[i][4], acc[i][5], acc[i][6], acc[i][7]);
        }
    }
}

// ---- layer1 aggregate (gather) + self + bias + relu + GEMM2, all fused ---
// one warp per node; lane holds float4 (cols lane*4 .. lane*4+3)
__global__ __launch_bounds__(256) void k_agg1(const float* __restrict__ b1,
                                              const float* __restrict__ W2) {
    int node = (blockIdx.x * blockDim.x + threadIdx.x) >> 5;
    int lane = threadIdx.x & 31;
    if (node >= NN) return;

    int start = g_off[node];
    int cnt   = g_cnt[node];

    float4 acc = make_float4(0.f, 0.f, 0.f, 0.f);
    const int2* eb = g_ebuf + start;
    for (int e = 0; e < cnt; e++) {
        int2 p = __ldg(eb + e);
        float norm = __int_as_float(p.y);
        float4 v = __ldg(((const float4*)(g_xw + (size_t)p.x * HID)) + lane);
        acc.x = fmaf(v.x, norm, acc.x);
        acc.y = fmaf(v.y, norm, acc.y);
        acc.z = fmaf(v.z, norm, acc.z);
        acc.w = fmaf(v.w, norm, acc.w);
    }
    // self loop
    float di = g_dinv[node];
    float sn = di * di;
    float4 sv = __ldg(((const float4*)(g_xw + (size_t)node * HID)) + lane);
    acc.x = fmaf(sv.x, sn, acc.x);
    acc.y = fmaf(sv.y, sn, acc.y);
    acc.z = fmaf(sv.z, sn, acc.z);
    acc.w = fmaf(sv.w, sn, acc.w);
    // bias + relu -> h1 in registers
    float4 bb = __ldg(((const float4*)b1) + lane);
    float4 h;
    h.x = fmaxf(acc.x + bb.x, 0.f);
    h.y = fmaxf(acc.y + bb.y, 0.f);
    h.z = fmaxf(acc.z + bb.z, 0.f);
    h.w = fmaxf(acc.w + bb.w, 0.f);

    // t2 = h1 @ W2  (warp reduction per output channel)
    int k0 = lane * 4;
    #pragma unroll
    for (int j = 0; j < OC; j++) {
        float p = h.x * __ldg(&W2[(k0 + 0) * OC + j])
                + h.y * __ldg(&W2[(k0 + 1) * OC + j])
                + h.z * __ldg(&W2[(k0 + 2) * OC + j])
                + h.w * __ldg(&W2[(k0 + 3) * OC + j]);
        p += __shfl_down_sync(0xFFFFFFFFu, p, 16);
        p += __shfl_down_sync(0xFFFFFFFFu, p, 8);
        p += __shfl_down_sync(0xFFFFFFFFu, p, 4);
        p += __shfl_down_sync(0xFFFFFFFFu, p, 2);
        p += __shfl_down_sync(0xFFFFFFFFu, p, 1);
        if (lane == 0) g_t2[(size_t)node * OC + j] = p;
    }
}

// ---- layer2 aggregate (gather) + self + bias, writes d_out directly ------
__global__ __launch_bounds__(256) void k_agg2(const float* __restrict__ b2,
                                              float* __restrict__ out) {
    int node = (blockIdx.x * blockDim.x + threadIdx.x) >> 5;
    int lane = threadIdx.x & 31;
    if (node >= NN) return;

    int start = g_off[node];
    int cnt   = g_cnt[node];

    float acc = 0.f;
    const int2* eb = g_ebuf + start;
    for (int e = 0; e < cnt; e++) {
        int2 p = __ldg(eb + e);
        if (lane < OC) {
            float norm = __int_as_float(p.y);
            acc = fmaf(__ldg(&g_t2[(size_t)p.x * OC + lane]), norm, acc);
        }
    }
    if (lane < OC) {
        float di = g_dinv[node];
        acc = fmaf(__ldg(&g_t2[(size_t)node * OC + lane]), di * di, acc);
        out[(size_t)node * OC + lane] = acc + __ldg(&b2[lane]);
    }
}

// ---------------- launch -------------------------------------------------
extern "C" void kernel_launch(void* const* d_in, const int* in_sizes, int n_in,
                              void* d_out, int out_size) {
    const float* x    = (const float*)d_in[0];
    const void*  eidx = d_in[1];
    // d_in[2] = labels (unused)
    const float* anch = (const float*)d_in[3];
    const float* W1   = (const float*)d_in[4];
    const float* b1   = (const float*)d_in[5];
    const float* W2   = (const float*)d_in[6];
    const float* b2   = (const float*)d_in[7];
    float*       out  = (float*)d_out;

    const int E = in_sizes[1] / 2;

    k_detect<<<1, 32>>>(eidx);
    k_zero  <<<(NN + 255) / 256, 256>>>();
    k_count <<<(E + 255) / 256, 256>>>(eidx, E);
    k_scan1 <<<NB_SCAN, 256>>>();
    k_scan2 <<<1, 512>>>();
    k_scan3 <<<(NN + 255) / 256, 256>>>();
    k_bucket<<<(E + 255) / 256, 256>>>(eidx, E);

    k_gemm1 <<<(NN + G1_BM - 1) / G1_BM, 256>>>(x, anch, W1);

    {
        long long threads = (long long)NN * 32;
        unsigned blocks = (unsigned)((threads + 255) / 256);
        k_agg1<<<blocks, 256>>>(b1, W2);
        k_agg2<<<blocks, 256>>>(b2, out);
    }
}

// round 3
// speedup vs baseline: 1.6222x; 1.0565x over previous
#include <cuda_runtime.h>
#include <cuda_fp16.h>
#include <stdint.h>

// Problem constants (fixed by the dataset)
#define NN      100000
#define EE_MAX  1600000
#define IC      128
#define HID     128
#define OC      10
#define NB_SCAN 391          // ceil(NN/256)

// ---------------- static scratch (no allocations allowed) ----------------
__device__ float  g_dinv[NN];
__device__ __half g_xwh[(size_t)NN * HID];   // h0 @ W1, fp16
__device__ float  g_t2 [(size_t)NN * OC];    // h1 @ W2 (pre-aggregation)
__device__ int    g_cnt [NN];                // in-degree (excl. self loop)
__device__ int    g_excl[NN];                // within-block exclusive scan
__device__ int    g_off [NN];                // CSR row start
__device__ int    g_cur [NN];                // bucket cursor
__device__ int    g_btot[NB_SCAN];
__device__ int    g_boff[NB_SCAN];
__device__ int2   g_ebuf[EE_MAX];            // {src, norm-as-bits} bucketed by dst
__device__ int    g_is64;

// ---------------- dtype detection for edge_index (int64 vs int32) --------
__global__ void k_detect(const void* eidx) {
    if (threadIdx.x == 0 && blockIdx.x == 0) {
        const unsigned long long* p = (const unsigned long long*)eidx;
        int is64 = 1;
        for (int i = 0; i < 256; i++) {
            if (p[i] >> 32) { is64 = 0; break; }  // ids < 100000 -> high word 0 iff i64
        }
        g_is64 = is64;
    }
}

__device__ __forceinline__ int edge_at(const void* eidx, long long off) {
    return g_is64 ? (int)((const long long*)eidx)[off]
                  : ((const int*)eidx)[off];
}

// ---------------- CSR build ----------------------------------------------
__global__ void k_zero() {
    int i = blockIdx.x * blockDim.x + threadIdx.x;
    if (i < NN) g_cnt[i] = 0;
}

__global__ void k_count(const void* __restrict__ eidx, int E) {
    int e = blockIdx.x * blockDim.x + threadIdx.x;
    if (e >= E) return;
    int d = edge_at(eidx, (long long)E + e);
    atomicAdd(&g_cnt[d], 1);
}

// per-block inclusive scan of counts; emit within-block exclusive + block total
__global__ __launch_bounds__(256) void k_scan1() {
    __shared__ int sh[256];
    int tid = threadIdx.x;
    int i = blockIdx.x * 256 + tid;
    int c = (i < NN) ? g_cnt[i] : 0;
    sh[tid] = c;
    __syncthreads();
    #pragma unroll
    for (int o = 1; o < 256; o <<= 1) {
        int v = (tid >= o) ? sh[tid - o] : 0;
        __syncthreads();
        sh[tid] += v;
        __syncthreads();
    }
    if (i < NN) g_excl[i] = sh[tid] - c;
    if (tid == 255) g_btot[blockIdx.x] = sh[255];
}

// scan of block totals (single block)
__global__ __launch_bounds__(512) void k_scan2() {
    __shared__ int sh[512];
    int tid = threadIdx.x;
    int t = (tid < NB_SCAN) ? g_btot[tid] : 0;
    sh[tid] = t;
    __syncthreads();
    #pragma unroll
    for (int o = 1; o < 512; o <<= 1) {
        int v = (tid >= o) ? sh[tid - o] : 0;
        __syncthreads();
        sh[tid] += v;
        __syncthreads();
    }
    if (tid < NB_SCAN) g_boff[tid] = sh[tid] - t;
}

// finalize offsets, cursors, dinv
__global__ void k_scan3() {
    int i = blockIdx.x * blockDim.x + threadIdx.x;
    if (i >= NN) return;
    int off = g_excl[i] + g_boff[i >> 8];
    g_off[i] = off;
    g_cur[i] = off;
    g_dinv[i] = rsqrtf((float)g_cnt[i] + 1.0f);  // +1 self loop
}

__global__ void k_bucket(const void* __restrict__ eidx, int E) {
    int e = blockIdx.x * blockDim.x + threadIdx.x;
    if (e >= E) return;
    int s = edge_at(eidx, e);
    int d = edge_at(eidx, (long long)E + e);
    int pos = atomicAdd(&g_cur[d], 1);
    float norm = g_dinv[s] * g_dinv[d];
    g_ebuf[pos] = make_int2(s, __float_as_int(norm));
}

// ---------------- GEMM1: g_xwh = [x - a, a] @ W1  (M=100k, N=128, K=256) --
#define G1_BM 128
#define G1_BN 128
#define G1_BK 8
__global__ __launch_bounds__(256) void k_gemm1(const float* __restrict__ x,
                                               const float* __restrict__ anch,
                                               const float* __restrict__ W1) {
    __shared__ float As[G1_BK][G1_BM];
    __shared__ float Bs[G1_BK][G1_BN];

    const int tid = threadIdx.x;
    const int row0 = blockIdx.x * G1_BM;
    const int tx = tid & 15;       // col tile: tx*8 .. tx*8+7
    const int ty = tid >> 4;       // row tile: ty*8 .. ty*8+7

    const int ar = tid >> 1;         // A loader: row
    const int ak = (tid & 1) * 4;    //           k quad
    const int br = tid >> 5;         // B loader: row
    const int bc = (tid & 31) * 4;   //           col quad

    float acc[8][8];
    #pragma unroll
    for (int i = 0; i < 8; i++)
        #pragma unroll
        for (int j = 0; j < 8; j++) acc[i][j] = 0.f;

    for (int kt = 0; kt < 2 * IC; kt += G1_BK) {
        {
            int n = row0 + ar;
            int k = kt + ak;
            float4 v = make_float4(0.f, 0.f, 0.f, 0.f);
            if (n < NN) {
                if (k < IC) {
                    float4 a = __ldg((const float4*)(x    + (size_t)n * IC + k));
                    float4 b = __ldg((const float4*)(anch + (size_t)n * IC + k));
                    v = make_float4(a.x - b.x, a.y - b.y, a.z - b.z, a.w - b.w);
                } else {
                    v = __ldg((const float4*)(anch + (size_t)n * IC + (k - IC)));
                }
            }
            As[ak + 0][ar] = v.x;
            As[ak + 1][ar] = v.y;
            As[ak + 2][ar] = v.z;
            As[ak + 3][ar] = v.w;
        }
        {
            float4 w = __ldg((const float4*)(W1 + (size_t)(kt + br) * G1_BN + bc));
            *((float4*)&Bs[br][bc]) = w;
        }
        __syncthreads();

        #pragma unroll
        for (int k = 0; k < G1_BK; k++) {
            float a[8], b[8];
            *((float4*)(a + 0)) = *((const float4*)&As[k][ty * 8 + 0]);
            *((float4*)(a + 4)) = *((const float4*)&As[k][ty * 8 + 4]);
            *((float4*)(b + 0)) = *((const float4*)&Bs[k][tx * 8 + 0]);
            *((float4*)(b + 4)) = *((const float4*)&Bs[k][tx * 8 + 4]);
            #pragma unroll
            for (int i = 0; i < 8; i++)
                #pragma unroll
                for (int j = 0; j < 8; j++)
                    acc[i][j] = fmaf(a[i], b[j], acc[i][j]);
        }
        __syncthreads();
    }

    #pragma unroll
    for (int i = 0; i < 8; i++) {
        int n = row0 + ty * 8 + i;
        if (n < NN) {
            __half2 h0 = __floats2half2_rn(acc[i][0], acc[i][1]);
            __half2 h1 = __floats2half2_rn(acc[i][2], acc[i][3]);
            __half2 h2 = __floats2half2_rn(acc[i][4], acc[i][5]);
            __half2 h3 = __floats2half2_rn(acc[i][6], acc[i][7]);
            uint4 pack;
            pack.x = *(unsigned*)&h0;
            pack.y = *(unsigned*)&h1;
            pack.z = *(unsigned*)&h2;
            pack.w = *(unsigned*)&h3;
            *((uint4*)(g_xwh + (size_t)n * HID + tx * 8)) = pack;
        }
    }
}

// ---- helpers -------------------------------------------------------------
__device__ __forceinline__ float4 ld_h4(const __half* base, size_t row, int lane) {
    uint2 u = __ldg((const uint2*)(base + row * HID) + lane);
    float2 f0 = __half22float2(*(__half2*)&u.x);
    float2 f1 = __half22float2(*(__half2*)&u.y);
    return make_float4(f0.x, f0.y, f1.x, f1.y);
}
__device__ __forceinline__ void fma4(float4& acc, float4 v, float n) {
    acc.x = fmaf(v.x, n, acc.x);
    acc.y = fmaf(v.y, n, acc.y);
    acc.z = fmaf(v.z, n, acc.z);
    acc.w = fmaf(v.w, n, acc.w);
}

// ---- layer1 aggregate (gather) + self + bias + relu + GEMM2, all fused ---
// one warp per node; lane holds 4 cols (lane*4 .. lane*4+3)
__global__ __launch_bounds__(256) void k_agg1(const float* __restrict__ b1,
                                              const float* __restrict__ W2) {
    int node = (blockIdx.x * blockDim.x + threadIdx.x) >> 5;
    int lane = threadIdx.x & 31;
    if (node >= NN) return;

    int start = g_off[node];
    int cnt   = g_cnt[node];
    const int2* eb = g_ebuf + start;

    float4 acc0 = make_float4(0.f, 0.f, 0.f, 0.f);
    float4 acc1 = make_float4(0.f, 0.f, 0.f, 0.f);

    int e = 0;
    for (; e + 4 <= cnt; e += 4) {
        int2 p0 = __ldg(eb + e + 0);
        int2 p1 = __ldg(eb + e + 1);
        int2 p2 = __ldg(eb + e + 2);
        int2 p3 = __ldg(eb + e + 3);
        float4 v0 = ld_h4(g_xwh, (size_t)p0.x, lane);
        float4 v1 = ld_h4(g_xwh, (size_t)p1.x, lane);
        float4 v2 = ld_h4(g_xwh, (size_t)p2.x, lane);
        float4 v3 = ld_h4(g_xwh, (size_t)p3.x, lane);
        fma4(acc0, v0, __int_as_float(p0.y));
        fma4(acc1, v1, __int_as_float(p1.y));
        fma4(acc0, v2, __int_as_float(p2.y));
        fma4(acc1, v3, __int_as_float(p3.y));
    }
    for (; e < cnt; e++) {
        int2 p = __ldg(eb + e);
        float4 v = ld_h4(g_xwh, (size_t)p.x, lane);
        fma4(acc0, v, __int_as_float(p.y));
    }

    // self loop
    float di = g_dinv[node];
    float4 sv = ld_h4(g_xwh, (size_t)node, lane);
    fma4(acc1, sv, di * di);

    acc0.x += acc1.x; acc0.y += acc1.y; acc0.z += acc1.z; acc0.w += acc1.w;

    // bias + relu -> h1 in registers
    float4 bb = __ldg(((const float4*)b1) + lane);
    float4 h;
    h.x = fmaxf(acc0.x + bb.x, 0.f);
    h.y = fmaxf(acc0.y + bb.y, 0.f);
    h.z = fmaxf(acc0.z + bb.z, 0.f);
    h.w = fmaxf(acc0.w + bb.w, 0.f);

    // t2 = h1 @ W2  (warp reduction per output channel)
    int k0 = lane * 4;
    #pragma unroll
    for (int j = 0; j < OC; j++) {
        float p = h.x * __ldg(&W2[(k0 + 0) * OC + j])
                + h.y * __ldg(&W2[(k0 + 1) * OC + j])
                + h.z * __ldg(&W2[(k0 + 2) * OC + j])
                + h.w * __ldg(&W2[(k0 + 3) * OC + j]);
        p += __shfl_down_sync(0xFFFFFFFFu, p, 16);
        p += __shfl_down_sync(0xFFFFFFFFu, p, 8);
        p += __shfl_down_sync(0xFFFFFFFFu, p, 4);
        p += __shfl_down_sync(0xFFFFFFFFu, p, 2);
        p += __shfl_down_sync(0xFFFFFFFFu, p, 1);
        if (lane == 0) g_t2[(size_t)node * OC + j] = p;
    }
}

// ---- layer2 aggregate (gather) + self + bias, writes d_out directly ------
__global__ __launch_bounds__(256) void k_agg2(const float* __restrict__ b2,
                                              float* __restrict__ out) {
    int node = (blockIdx.x * blockDim.x + threadIdx.x) >> 5;
    int lane = threadIdx.x & 31;
    if (node >= NN) return;

    int start = g_off[node];
    int cnt   = g_cnt[node];
    const int2* eb = g_ebuf + start;

    float acc0 = 0.f, acc1 = 0.f;
    int e = 0;
    for (; e + 2 <= cnt; e += 2) {
        int2 p0 = __ldg(eb + e + 0);
        int2 p1 = __ldg(eb + e + 1);
        if (lane < OC) {
            float t0 = __ldg(&g_t2[(size_t)p0.x * OC + lane]);
            float t1 = __ldg(&g_t2[(size_t)p1.x * OC + lane]);
            acc0 = fmaf(t0, __int_as_float(p0.y), acc0);
            acc1 = fmaf(t1, __int_as_float(p1.y), acc1);
        }
    }
    for (; e < cnt; e++) {
        int2 p = __ldg(eb + e);
        if (lane < OC) {
            acc0 = fmaf(__ldg(&g_t2[(size_t)p.x * OC + lane]), __int_as_float(p.y), acc0);
        }
    }
    if (lane < OC) {
        float di = g_dinv[node];
        float acc = acc0 + acc1;
        acc = fmaf(__ldg(&g_t2[(size_t)node * OC + lane]), di * di, acc);
        out[(size_t)node * OC + lane] = acc + __ldg(&b2[lane]);
    }
}

// ---------------- launch -------------------------------------------------
extern "C" void kernel_launch(void* const* d_in, const int* in_sizes, int n_in,
                              void* d_out, int out_size) {
    const float* x    = (const float*)d_in[0];
    const void*  eidx = d_in[1];
    // d_in[2] = labels (unused)
    const float* anch = (const float*)d_in[3];
    const float* W1   = (const float*)d_in[4];
    const float* b1   = (const float*)d_in[5];
    const float* W2   = (const float*)d_in[6];
    const float* b2   = (const float*)d_in[7];
    float*       out  = (float*)d_out;

    const int E = in_sizes[1] / 2;

    // NOTE: launch order puts k_gemm1 at stream position 3 so the ncu capture
    // (which has landed on position 3 in both prior rounds) profiles it.
    k_detect<<<1, 32>>>(eidx);                       // 0
    k_zero  <<<(NN + 255) / 256, 256>>>();           // 1
    k_count <<<(E + 255) / 256, 256>>>(eidx, E);     // 2
    k_gemm1 <<<(NN + G1_BM - 1) / G1_BM, 256>>>(x, anch, W1);  // 3 <- profiled
    k_scan1 <<<NB_SCAN, 256>>>();                    // 4
    k_scan2 <<<1, 512>>>();                          // 5
    k_scan3 <<<(NN + 255) / 256, 256>>>();           // 6
    k_bucket<<<(E + 255) / 256, 256>>>(eidx, E);     // 7

    {
        long long threads = (long long)NN * 32;
        unsigned blocks = (unsigned)((threads + 255) / 256);
        k_agg1<<<blocks, 256>>>(b1, W2);             // 8
        k_agg2<<<blocks, 256>>>(b2, out);            // 9
    }
}

// round 4
// speedup vs baseline: 2.2708x; 1.3999x over previous
#include <cuda_runtime.h>
#include <cuda_fp16.h>
#include <stdint.h>

// Problem constants (fixed by the dataset)
#define NN      100000
#define EE_MAX  1600000
#define IC      128
#define HID     128
#define OC      10
#define NB_SCAN 391          // ceil(NN/256)

// ---------------- static scratch (no allocations allowed) ----------------
__device__ float  g_dinv[NN];
__device__ __align__(16) __half g_xwh[(size_t)NN * HID];  // h0 @ W1, fp16
__device__ __align__(16) __half g_w1h[(size_t)HID * 2 * IC]; // W1^T as [N=128][K=256] fp16
__device__ float  g_t2 [(size_t)NN * OC];    // h1 @ W2 (pre-aggregation)
__device__ int    g_cnt [NN];
__device__ int    g_excl[NN];
__device__ int    g_off [NN];
__device__ int    g_cur [NN];
__device__ int    g_btot[NB_SCAN];
__device__ int    g_boff[NB_SCAN];
__device__ int2   g_ebuf[EE_MAX];            // {src, norm-as-bits} bucketed by dst
__device__ int    g_is64;

// ---------------- dtype detection for edge_index (int64 vs int32) --------
__global__ void k_detect(const void* eidx) {
    if (threadIdx.x == 0 && blockIdx.x == 0) {
        const unsigned long long* p = (const unsigned long long*)eidx;
        int is64 = 1;
        for (int i = 0; i < 256; i++) {
            if (p[i] >> 32) { is64 = 0; break; }
        }
        g_is64 = is64;
    }
}

__device__ __forceinline__ int edge_at(const void* eidx, long long off) {
    return g_is64 ? (int)((const long long*)eidx)[off]
                  : ((const int*)eidx)[off];
}

// ---------------- W1 convert + transpose: g_w1h[n][k] = W1[k][n] ----------
__global__ void k_w1cvt(const float* __restrict__ W1) {
    int idx = blockIdx.x * blockDim.x + threadIdx.x;   // 32768
    if (idx >= HID * 2 * IC) return;
    int n = idx >> 8;          // 0..127
    int k = idx & 255;         // 0..255
    g_w1h[idx] = __float2half(__ldg(&W1[(size_t)k * HID + n]));
}

// ---------------- CSR build ----------------------------------------------
__global__ void k_zero() {
    int i = blockIdx.x * blockDim.x + threadIdx.x;
    if (i < NN) g_cnt[i] = 0;
}

__global__ void k_count(const void* __restrict__ eidx, int E) {
    int e = blockIdx.x * blockDim.x + threadIdx.x;
    if (e >= E) return;
    int d = edge_at(eidx, (long long)E + e);
    atomicAdd(&g_cnt[d], 1);
}

__global__ __launch_bounds__(256) void k_scan1() {
    __shared__ int sh[256];
    int tid = threadIdx.x;
    int i = blockIdx.x * 256 + tid;
    int c = (i < NN) ? g_cnt[i] : 0;
    sh[tid] = c;
    __syncthreads();
    #pragma unroll
    for (int o = 1; o < 256; o <<= 1) {
        int v = (tid >= o) ? sh[tid - o] : 0;
        __syncthreads();
        sh[tid] += v;
        __syncthreads();
    }
    if (i < NN) g_excl[i] = sh[tid] - c;
    if (tid == 255) g_btot[blockIdx.x] = sh[255];
}

__global__ __launch_bounds__(512) void k_scan2() {
    __shared__ int sh[512];
    int tid = threadIdx.x;
    int t = (tid < NB_SCAN) ? g_btot[tid] : 0;
    sh[tid] = t;
    __syncthreads();
    #pragma unroll
    for (int o = 1; o < 512; o <<= 1) {
        int v = (tid >= o) ? sh[tid - o] : 0;
        __syncthreads();
        sh[tid] += v;
        __syncthreads();
    }
    if (tid < NB_SCAN) g_boff[tid] = sh[tid] - t;
}

__global__ void k_scan3() {
    int i = blockIdx.x * blockDim.x + threadIdx.x;
    if (i >= NN) return;
    int off = g_excl[i] + g_boff[i >> 8];
    g_off[i] = off;
    g_cur[i] = off;
    g_dinv[i] = rsqrtf((float)g_cnt[i] + 1.0f);
}

__global__ void k_bucket(const void* __restrict__ eidx, int E) {
    int e = blockIdx.x * blockDim.x + threadIdx.x;
    if (e >= E) return;
    int s = edge_at(eidx, e);
    int d = edge_at(eidx, (long long)E + e);
    int pos = atomicAdd(&g_cur[d], 1);
    float norm = g_dinv[s] * g_dinv[d];
    g_ebuf[pos] = make_int2(s, __float_as_int(norm));
}

// ---------------- tensor-core GEMM1 ---------------------------------------
// g_xwh = [x - a, a] @ W1   M=100k, N=128, K=256, fp16 in / fp32 acc / fp16 out
#define TS 40   // shared tile stride in halves (80 B, 16B-aligned, conflict-spreading)

__device__ __forceinline__ uint32_t smem_u32(const void* p) {
    return (uint32_t)__cvta_generic_to_shared(p);
}
__device__ __forceinline__ void ldsm_x4(uint32_t* r, uint32_t addr) {
    asm volatile("ldmatrix.sync.aligned.m8n8.x4.shared.b16 {%0,%1,%2,%3}, [%4];"
                 : "=r"(r[0]), "=r"(r[1]), "=r"(r[2]), "=r"(r[3]) : "r"(addr));
}
__device__ __forceinline__ void ldsm_x2(uint32_t* r, uint32_t addr) {
    asm volatile("ldmatrix.sync.aligned.m8n8.x2.shared.b16 {%0,%1}, [%2];"
                 : "=r"(r[0]), "=r"(r[1]) : "r"(addr));
}
__device__ __forceinline__ void mma_16816(float* c, const uint32_t* a, const uint32_t* b) {
    asm volatile("mma.sync.aligned.m16n8k16.row.col.f32.f16.f16.f32 "
                 "{%0,%1,%2,%3}, {%4,%5,%6,%7}, {%8,%9}, {%0,%1,%2,%3};"
                 : "+f"(c[0]), "+f"(c[1]), "+f"(c[2]), "+f"(c[3])
                 : "r"(a[0]), "r"(a[1]), "r"(a[2]), "r"(a[3]), "r"(b[0]), "r"(b[1]));
}

__global__ __launch_bounds__(256) void k_gemm1(const float* __restrict__ x,
                                               const float* __restrict__ anch) {
    __shared__ __half As[128 * TS];
    __shared__ __half Bs[128 * TS];

    const int tid  = threadIdx.x;
    const int lane = tid & 31;
    const int wid  = tid >> 5;
    const int row0 = blockIdx.x * 128;
    const int wm = (wid >> 2) * 64;    // warp m origin in tile
    const int wn = (wid & 3) * 32;     // warp n origin

    float c[4][4][4];
    #pragma unroll
    for (int mt = 0; mt < 4; mt++)
        #pragma unroll
        for (int nt = 0; nt < 4; nt++)
            #pragma unroll
            for (int q = 0; q < 4; q++) c[mt][nt][q] = 0.f;

    // ldmatrix lane address components
    const int a_row = lane & 15;
    const int a_col = (lane >> 4) * 8;
    const int b_row = lane & 7;
    const int b_col = ((lane >> 3) & 1) * 8;

    for (int kt = 0; kt < 2 * IC; kt += 32) {
        // ---- A tile: 128 rows x 32 k (fp16), from fp32 [x-a | a] ----
        #pragma unroll
        for (int i = 0; i < 2; i++) {
            int gid = tid + i * 256;       // 0..511
            int row = gid >> 2;            // 0..127
            int kq  = (gid & 3) * 8;       // 0,8,16,24
            int n   = row0 + row;
            int k   = kt + kq;
            float4 va = make_float4(0.f, 0.f, 0.f, 0.f);
            float4 vb = make_float4(0.f, 0.f, 0.f, 0.f);
            if (n < NN) {
                if (k < IC) {
                    float4 x0 = __ldg((const float4*)(x    + (size_t)n * IC + k));
                    float4 x1 = __ldg((const float4*)(x    + (size_t)n * IC + k + 4));
                    float4 a0 = __ldg((const float4*)(anch + (size_t)n * IC + k));
                    float4 a1 = __ldg((const float4*)(anch + (size_t)n * IC + k + 4));
                    va = make_float4(x0.x - a0.x, x0.y - a0.y, x0.z - a0.z, x0.w - a0.w);
                    vb = make_float4(x1.x - a1.x, x1.y - a1.y, x1.z - a1.z, x1.w - a1.w);
                } else {
                    va = __ldg((const float4*)(anch + (size_t)n * IC + (k - IC)));
                    vb = __ldg((const float4*)(anch + (size_t)n * IC + (k - IC) + 4));
                }
            }
            __half2 h0 = __floats2half2_rn(va.x, va.y);
            __half2 h1 = __floats2half2_rn(va.z, va.w);
            __half2 h2 = __floats2half2_rn(vb.x, vb.y);
            __half2 h3 = __floats2half2_rn(vb.z, vb.w);
            uint4 pack;
            pack.x = *(unsigned*)&h0; pack.y = *(unsigned*)&h1;
            pack.z = *(unsigned*)&h2; pack.w = *(unsigned*)&h3;
            *(uint4*)&As[row * TS + kq] = pack;
        }
        // ---- B tile: 128 n-rows x 32 k (fp16) from pre-transposed W1 ----
        #pragma unroll
        for (int i = 0; i < 2; i++) {
            int gid = tid + i * 256;
            int row = gid >> 2;            // n
            int kq  = (gid & 3) * 8;
            uint4 w = *(const uint4*)(g_w1h + (size_t)row * 256 + kt + kq);
            *(uint4*)&Bs[row * TS + kq] = w;
        }
        __syncthreads();

        #pragma unroll
        for (int ks = 0; ks < 32; ks += 16) {
            uint32_t af[4][4], bf[4][2];
            #pragma unroll
            for (int mt = 0; mt < 4; mt++)
                ldsm_x4(af[mt], smem_u32(&As[(wm + mt * 16 + a_row) * TS + ks + a_col]));
            #pragma unroll
            for (int nt = 0; nt < 4; nt++)
                ldsm_x2(bf[nt], smem_u32(&Bs[(wn + nt * 8 + b_row) * TS + ks + b_col]));
            #pragma unroll
            for (int mt = 0; mt < 4; mt++)
                #pragma unroll
                for (int nt = 0; nt < 4; nt++)
                    mma_16816(c[mt][nt], af[mt], bf[nt]);
        }
        __syncthreads();
    }

    // ---- epilogue: fp32 acc -> fp16 pairs, direct global stores ----
    const int r  = lane >> 2;
    const int cp = (lane & 3) * 2;
    #pragma unroll
    for (int mt = 0; mt < 4; mt++) {
        #pragma unroll
        for (int nt = 0; nt < 4; nt++) {
            int ng  = row0 + wm + mt * 16 + r;
            int col = wn + nt * 8 + cp;
            if (ng < NN) {
                __half2 h = __floats2half2_rn(c[mt][nt][0], c[mt][nt][1]);
                *(__half2*)&g_xwh[(size_t)ng * HID + col] = h;
            }
            if (ng + 8 < NN) {
                __half2 h = __floats2half2_rn(c[mt][nt][2], c[mt][nt][3]);
                *(__half2*)&g_xwh[(size_t)(ng + 8) * HID + col] = h;
            }
        }
    }
}

// ---- helpers -------------------------------------------------------------
__device__ __forceinline__ float4 ld_h4(const __half* base, size_t row, int lane) {
    uint2 u = __ldg((const uint2*)(base + row * HID) + lane);
    float2 f0 = __half22float2(*(__half2*)&u.x);
    float2 f1 = __half22float2(*(__half2*)&u.y);
    return make_float4(f0.x, f0.y, f1.x, f1.y);
}
__device__ __forceinline__ void fma4(float4& acc, float4 v, float n) {
    acc.x = fmaf(v.x, n, acc.x);
    acc.y = fmaf(v.y, n, acc.y);
    acc.z = fmaf(v.z, n, acc.z);
    acc.w = fmaf(v.w, n, acc.w);
}

// ---- layer1 aggregate (gather) + self + bias + relu + GEMM2, all fused ---
__global__ __launch_bounds__(256) void k_agg1(const float* __restrict__ b1,
                                              const float* __restrict__ W2) {
    int node = (blockIdx.x * blockDim.x + threadIdx.x) >> 5;
    int lane = threadIdx.x & 31;
    if (node >= NN) return;

    int start = g_off[node];
    int cnt   = g_cnt[node];
    const int2* eb = g_ebuf + start;

    float4 acc0 = make_float4(0.f, 0.f, 0.f, 0.f);
    float4 acc1 = make_float4(0.f, 0.f, 0.f, 0.f);

    int e = 0;
    for (; e + 8 <= cnt; e += 8) {
        int2 p[8];
        #pragma unroll
        for (int j = 0; j < 8; j++) p[j] = __ldg(eb + e + j);
        float4 v[8];
        #pragma unroll
        for (int j = 0; j < 8; j++) v[j] = ld_h4(g_xwh, (size_t)p[j].x, lane);
        #pragma unroll
        for (int j = 0; j < 8; j++)
            fma4((j & 1) ? acc1 : acc0, v[j], __int_as_float(p[j].y));
    }
    for (; e < cnt; e++) {
        int2 p = __ldg(eb + e);
        float4 v = ld_h4(g_xwh, (size_t)p.x, lane);
        fma4(acc0, v, __int_as_float(p.y));
    }

    // self loop
    float di = g_dinv[node];
    float4 sv = ld_h4(g_xwh, (size_t)node, lane);
    fma4(acc1, sv, di * di);

    acc0.x += acc1.x; acc0.y += acc1.y; acc0.z += acc1.z; acc0.w += acc1.w;

    // bias + relu -> h1 in registers
    float4 bb = __ldg(((const float4*)b1) + lane);
    float4 h;
    h.x = fmaxf(acc0.x + bb.x, 0.f);
    h.y = fmaxf(acc0.y + bb.y, 0.f);
    h.z = fmaxf(acc0.z + bb.z, 0.f);
    h.w = fmaxf(acc0.w + bb.w, 0.f);

    // t2 = h1 @ W2  (warp reduction per output channel)
    int k0 = lane * 4;
    #pragma unroll
    for (int j = 0; j < OC; j++) {
        float p = h.x * __ldg(&W2[(k0 + 0) * OC + j])
                + h.y * __ldg(&W2[(k0 + 1) * OC + j])
                + h.z * __ldg(&W2[(k0 + 2) * OC + j])
                + h.w * __ldg(&W2[(k0 + 3) * OC + j]);
        p += __shfl_down_sync(0xFFFFFFFFu, p, 16);
        p += __shfl_down_sync(0xFFFFFFFFu, p, 8);
        p += __shfl_down_sync(0xFFFFFFFFu, p, 4);
        p += __shfl_down_sync(0xFFFFFFFFu, p, 2);
        p += __shfl_down_sync(0xFFFFFFFFu, p, 1);
        if (lane == 0) g_t2[(size_t)node * OC + j] = p;
    }
}

// ---- layer2 aggregate (gather) + self + bias, writes d_out directly ------
__global__ __launch_bounds__(256) void k_agg2(const float* __restrict__ b2,
                                              float* __restrict__ out) {
    int node = (blockIdx.x * blockDim.x + threadIdx.x) >> 5;
    int lane = threadIdx.x & 31;
    if (node >= NN) return;

    int start = g_off[node];
    int cnt   = g_cnt[node];
    const int2* eb = g_ebuf + start;

    float acc0 = 0.f, acc1 = 0.f;
    int e = 0;
    for (; e + 2 <= cnt; e += 2) {
        int2 p0 = __ldg(eb + e + 0);
        int2 p1 = __ldg(eb + e + 1);
        if (lane < OC) {
            float t0 = __ldg(&g_t2[(size_t)p0.x * OC + lane]);
            float t1 = __ldg(&g_t2[(size_t)p1.x * OC + lane]);
            acc0 = fmaf(t0, __int_as_float(p0.y), acc0);
            acc1 = fmaf(t1, __int_as_float(p1.y), acc1);
        }
    }
    for (; e < cnt; e++) {
        int2 p = __ldg(eb + e);
        if (lane < OC) {
            acc0 = fmaf(__ldg(&g_t2[(size_t)p.x * OC + lane]), __int_as_float(p.y), acc0);
        }
    }
    if (lane < OC) {
        float di = g_dinv[node];
        float acc = acc0 + acc1;
        acc = fmaf(__ldg(&g_t2[(size_t)node * OC + lane]), di * di, acc);
        out[(size_t)node * OC + lane] = acc + __ldg(&b2[lane]);
    }
}

// ---------------- launch -------------------------------------------------
extern "C" void kernel_launch(void* const* d_in, const int* in_sizes, int n_in,
                              void* d_out, int out_size) {
    const float* x    = (const float*)d_in[0];
    const void*  eidx = d_in[1];
    // d_in[2] = labels (unused)
    const float* anch = (const float*)d_in[3];
    const float* W1   = (const float*)d_in[4];
    const float* b1   = (const float*)d_in[5];
    const float* W2   = (const float*)d_in[6];
    const float* b2   = (const float*)d_in[7];
    float*       out  = (float*)d_out;

    const int E = in_sizes[1] / 2;

    // k_gemm1 kept at stream position 3 for the ncu capture window.
    k_detect<<<1, 32>>>(eidx);                                  // 0
    k_w1cvt <<<(HID * 2 * IC + 255) / 256, 256>>>(W1);          // 1
    k_zero  <<<(NN + 255) / 256, 256>>>();                      // 2
    k_gemm1 <<<(NN + 127) / 128, 256>>>(x, anch);               // 3 <- profiled
    k_count <<<(E + 255) / 256, 256>>>(eidx, E);                // 4
    k_scan1 <<<NB_SCAN, 256>>>();                               // 5
    k_scan2 <<<1, 512>>>();                                     // 6
    k_scan3 <<<(NN + 255) / 256, 256>>>();                      // 7
    k_bucket<<<(E + 255) / 256, 256>>>(eidx, E);                // 8

    {
        long long threads = (long long)NN * 32;
        unsigned blocks = (unsigned)((threads + 255) / 256);
        k_agg1<<<blocks, 256>>>(b1, W2);                        // 9
        k_agg2<<<blocks, 256>>>(b2, out);                       // 10
    }
}